// round 7
// baseline (speedup 1.0000x reference)
#include <cuda_runtime.h>
#include <cuda_fp16.h>

#define N_NODES 50000
#define N_EDGES 800000
#define D 64
#define SCAN_BLOCKS 196
#define N_TILES 391              // ceil(50000/128)

// ---------------- scratch (device globals; no allocs allowed) ----------------
// Mutable state is zero at process start (static init) and re-zeroed by
// fill_kernel each replay, so every graph replay sees identical initial state.
__device__ int                g_deg[N_NODES];
__device__ int                g_start[N_NODES + 1];
__device__ int                g_rank[N_EDGES];
__device__ unsigned long long g_blk_pack[256];        // (flag<<32)|value
__device__ int2               g_edges[N_EDGES];       // (src, weight) grouped by dst
__device__ uint4              g_featH4[N_NODES * 8];  // fp16 features, 8 halves/uint4
__device__ float4             g_neighbor[N_NODES * 16];

// ---------------------------------------------------------------------------
// K1: fp32->fp16 feature convert + rank-capturing destination histogram.
// ---------------------------------------------------------------------------
__global__ void conv_hist_kernel(const float4* __restrict__ feat4,
                                 const int4*   __restrict__ edst4,
                                 int4*         __restrict__ rank4) {
    int i = blockIdx.x * blockDim.x + threadIdx.x;
    if (i < N_NODES * 8) {
        float4 a = __ldg(feat4 + (size_t)i * 2);
        float4 b = __ldg(feat4 + (size_t)i * 2 + 1);
        uint4 o;
        *(__half2*)&o.x = __floats2half2_rn(a.x, a.y);
        *(__half2*)&o.y = __floats2half2_rn(a.z, a.w);
        *(__half2*)&o.z = __floats2half2_rn(b.x, b.y);
        *(__half2*)&o.w = __floats2half2_rn(b.z, b.w);
        g_featH4[i] = o;
    }
    if (i < N_EDGES / 4) {
        int4 d = __ldg(edst4 + i);
        int4 r;
        r.x = atomicAdd(&g_deg[d.x], 1);
        r.y = atomicAdd(&g_deg[d.y], 1);
        r.z = atomicAdd(&g_deg[d.z], 1);
        r.w = atomicAdd(&g_deg[d.w], 1);
        rank4[i] = r;
    }
}

// ---------------------------------------------------------------------------
// K2: single-pass exclusive scan (decoupled lookback), 196 blocks x 256
// ---------------------------------------------------------------------------
__device__ __forceinline__ int block_incl_scan_256(int v, int t, int* warp_sums) {
    int x = v;
#pragma unroll
    for (int off = 1; off < 32; off <<= 1) {
        int y = __shfl_up_sync(0xffffffffu, x, off);
        if ((t & 31) >= off) x += y;
    }
    if ((t & 31) == 31) warp_sums[t >> 5] = x;
    __syncthreads();
    if (t < 8) {
        int s = warp_sums[t];
#pragma unroll
        for (int off = 1; off < 8; off <<= 1) {
            int y = __shfl_up_sync(0x000000ffu, s, off);
            if (t >= off) s += y;
        }
        warp_sums[t] = s;
    }
    __syncthreads();
    if (t >= 32) x += warp_sums[(t >> 5) - 1];
    return x;
}

__global__ void scan_kernel() {
    __shared__ int warp_sums[8];
    __shared__ int s_agg;
    __shared__ int s_excl;
    int t = threadIdx.x, bid = blockIdx.x;
    int i = bid * 256 + t;

    int v = (i < N_NODES) ? g_deg[i] : 0;
    int incl = block_incl_scan_256(v, t, warp_sums);
    if (t == 255) s_agg = incl;
    __syncthreads();
    int agg = s_agg;

    if (t == 0) {
        unsigned long long p = (bid == 0)
            ? ((2ULL << 32) | (unsigned)agg)
            : ((1ULL << 32) | (unsigned)agg);
        atomicExch(&g_blk_pack[bid], p);
        if (bid == 0) s_excl = 0;
    }
    if (bid > 0 && t < 32) {
        int excl = 0;
        int look = bid - 1;
        while (true) {
            int idx = look - t;
            unsigned long long pk = (idx >= 0) ? atomicAdd(&g_blk_pack[idx], 0ULL)
                                               : (2ULL << 32);
            int f   = (int)(pk >> 32);
            int val = (int)(pk & 0xffffffffULL);
            unsigned ready = __ballot_sync(0xffffffffu, f >= 1);
            if (ready != 0xffffffffu) continue;
            unsigned pre = __ballot_sync(0xffffffffu, f == 2);
            if (pre) {
                int firstp = __ffs(pre) - 1;
                int contrib = (t <= firstp) ? val : 0;
#pragma unroll
                for (int o = 16; o; o >>= 1) contrib += __shfl_xor_sync(0xffffffffu, contrib, o);
                excl += contrib;
                break;
            } else {
                int contrib = val;
#pragma unroll
                for (int o = 16; o; o >>= 1) contrib += __shfl_xor_sync(0xffffffffu, contrib, o);
                excl += contrib;
                look -= 32;
            }
        }
        if (t == 0) {
            atomicExch(&g_blk_pack[bid], (2ULL << 32) | (unsigned)(excl + agg));
            s_excl = excl;
        }
    }
    __syncthreads();
    int base = s_excl;
    if (i < N_NODES) g_start[i] = base + incl - v;
    if (i == 0) g_start[N_NODES] = N_EDGES;
}

// ---------------------------------------------------------------------------
// K3: atomic-free CSR fill (slot = g_start[dst] + rank) + state re-zero.
// ---------------------------------------------------------------------------
__global__ void fill_kernel(const int4*   __restrict__ esrc4,
                            const int4*   __restrict__ edst4,
                            const float4* __restrict__ ew4,
                            const int4*   __restrict__ rank4) {
    int i = blockIdx.x * blockDim.x + threadIdx.x;
    if (i < N_EDGES / 4) {
        int4   s = __ldg(esrc4 + i);
        int4   d = __ldg(edst4 + i);
        float4 w = __ldg(ew4 + i);
        int4   r = __ldg(rank4 + i);
        g_edges[g_start[d.x] + r.x] = make_int2(s.x, __float_as_int(w.x));
        g_edges[g_start[d.y] + r.y] = make_int2(s.y, __float_as_int(w.y));
        g_edges[g_start[d.z] + r.z] = make_int2(s.z, __float_as_int(w.z));
        g_edges[g_start[d.w] + r.w] = make_int2(s.w, __float_as_int(w.w));
    }
    if (i < N_NODES) g_deg[i] = 0;
    if (i < 256) g_blk_pack[i] = 0ULL;
}

// ---------------------------------------------------------------------------
// K4: warp-per-node gather. lane = (esub 0..3, chunk 0..7):
// 4 esub groups walk 4 edges in parallel, chunk lanes split the 128B fp16 row.
// Zero divergence (trip counts differ by <=1 across lanes), x2 unroll.
// Cross-esub reduction via shfl_xor(8,16); lanes 0..7 write the row.
// ---------------------------------------------------------------------------
__device__ __forceinline__ void edge_acc(float* a, int2 r, int chunk) {
    uint4 h = __ldg(&g_featH4[(size_t)r.x * 8 + chunk]);
    float w = __int_as_float(r.y);
    float2 p0 = __half22float2(*(__half2*)&h.x);
    float2 p1 = __half22float2(*(__half2*)&h.y);
    float2 p2 = __half22float2(*(__half2*)&h.z);
    float2 p3 = __half22float2(*(__half2*)&h.w);
    a[0] += w * p0.x; a[1] += w * p0.y;
    a[2] += w * p1.x; a[3] += w * p1.y;
    a[4] += w * p2.x; a[5] += w * p2.y;
    a[6] += w * p3.x; a[7] += w * p3.y;
}

__global__ void gather_kernel() {
    int gwarp = (blockIdx.x * blockDim.x + threadIdx.x) >> 5;
    if (gwarp >= N_NODES) return;
    int lane  = threadIdx.x & 31;
    int esub  = lane >> 3;     // 0..3: which edge of the group of 4
    int chunk = lane & 7;      // 0..7: which 8-half slice of the row

    int j0 = g_start[gwarp];
    int j1 = g_start[gwarp + 1];

    float a[8] = {0.f, 0.f, 0.f, 0.f, 0.f, 0.f, 0.f, 0.f};
    int j = j0 + esub;
    // x2 unroll: 2 records + 2 feature rows in flight per lane
    for (; j + 4 < j1; j += 8) {
        int2 r0 = __ldg(&g_edges[j]);
        int2 r1 = __ldg(&g_edges[j + 4]);
        edge_acc(a, r0, chunk);
        edge_acc(a, r1, chunk);
    }
    if (j < j1) edge_acc(a, __ldg(&g_edges[j]), chunk);

    // reduce over the 4 esub groups (lane bits 3 and 4)
#pragma unroll
    for (int i = 0; i < 8; i++) {
        a[i] += __shfl_xor_sync(0xffffffffu, a[i], 8);
        a[i] += __shfl_xor_sync(0xffffffffu, a[i], 16);
    }
    if (esub == 0) {
        g_neighbor[(size_t)gwarp * 16 + chunk * 2]     = make_float4(a[0], a[1], a[2], a[3]);
        g_neighbor[(size_t)gwarp * 16 + chunk * 2 + 1] = make_float4(a[4], a[5], a[6], a[7]);
    }
}

// ---------------------------------------------------------------------------
// K5: GEMM + bias + L2-normalize, k-split staging for 3 blocks/SM.
// 391 blocks x 256 threads, 128-node tile each (single wave at occ 3).
// ---------------------------------------------------------------------------
#define XP 68
#define WP 68
#define GEMM_SMEM ((128 * XP + 128 * WP) * 4)

#define FFMA2(acc, a, b) \
    asm("fma.rn.f32x2 %0, %1, %2, %0;" : "+l"(acc) : "l"(a), "l"(b))
#define PACK2(dst, lo, hi) \
    asm("mov.b64 %0, {%1, %2};" : "=l"(dst) : "f"(lo), "f"(hi))
#define UNPACK2(lo, hi, src) \
    asm("mov.b64 {%0, %1}, %2;" : "=f"(lo), "=f"(hi) : "l"(src))

__global__ __launch_bounds__(256, 3)
void gemm_norm_kernel(const float4* __restrict__ feat4,
                      const float*  __restrict__ W,
                      const float*  __restrict__ bias,
                      float4*       __restrict__ out4) {
    extern __shared__ float sm[];
    float* xs = sm;              // [128 nodes][XP]  (one 64-k half at a time)
    float* ws = sm + 128 * XP;   // [128 k][WP]

    int t = threadIdx.x;
    int tx = t & 7;
    int ty = t >> 3;
    int node0 = blockIdx.x * 128;

    // W[o][k] (64x128 row-major) -> ws[k][o]
    for (int i = t; i < 64 * 128; i += 256) {
        int o = i >> 7, k = i & 127;
        ws[k * WP + o] = __ldg(W + i);
    }

    unsigned long long acc[4][4];
    {
        float4 bA = *reinterpret_cast<const float4*>(bias + 4 * tx);
        float4 bB = *reinterpret_cast<const float4*>(bias + 32 + 4 * tx);
        unsigned long long b0, b1, b2, b3;
        PACK2(b0, bA.x, bA.y); PACK2(b1, bA.z, bA.w);
        PACK2(b2, bB.x, bB.y); PACK2(b3, bB.z, bB.w);
#pragma unroll
        for (int i = 0; i < 4; i++) {
            acc[i][0] = b0; acc[i][1] = b1; acc[i][2] = b2; acc[i][3] = b3;
        }
    }

#pragma unroll
    for (int half = 0; half < 2; half++) {
        const float4* src = (half == 0) ? feat4 : g_neighbor;
        __syncthreads();   // previous half's reads done before overwrite
        for (int idx = t; idx < 128 * 16; idx += 256) {
            int n = idx >> 4, q = idx & 15;
            int node = node0 + n;
            float4 v = make_float4(0.f, 0.f, 0.f, 0.f);
            if (node < N_NODES) v = __ldg(src + (size_t)node * 16 + q);
            *reinterpret_cast<float4*>(xs + n * XP + q * 4) = v;
        }
        __syncthreads();

        const float* xrow = xs + ty * 4 * XP;
        const float* wsh  = ws + half * 64 * WP;
#pragma unroll 4
        for (int k = 0; k < 64; k++) {
            float4 wA = *reinterpret_cast<const float4*>(wsh + k * WP + 4 * tx);
            float4 wB = *reinterpret_cast<const float4*>(wsh + k * WP + 32 + 4 * tx);
            unsigned long long w0, w1, w2, w3;
            PACK2(w0, wA.x, wA.y); PACK2(w1, wA.z, wA.w);
            PACK2(w2, wB.x, wB.y); PACK2(w3, wB.z, wB.w);
#pragma unroll
            for (int i = 0; i < 4; i++) {
                float x = xrow[i * XP + k];
                unsigned long long xx;
                asm("mov.b64 %0, {%1, %1};" : "=l"(xx) : "f"(x));
                FFMA2(acc[i][0], xx, w0);
                FFMA2(acc[i][1], xx, w1);
                FFMA2(acc[i][2], xx, w2);
                FFMA2(acc[i][3], xx, w3);
            }
        }
    }

#pragma unroll
    for (int i = 0; i < 4; i++) {
        float a[8];
        UNPACK2(a[0], a[1], acc[i][0]);
        UNPACK2(a[2], a[3], acc[i][1]);
        UNPACK2(a[4], a[5], acc[i][2]);
        UNPACK2(a[6], a[7], acc[i][3]);
        float ss = 0.f;
#pragma unroll
        for (int j = 0; j < 8; j++) ss += a[j] * a[j];
        ss += __shfl_xor_sync(0xffffffffu, ss, 1);
        ss += __shfl_xor_sync(0xffffffffu, ss, 2);
        ss += __shfl_xor_sync(0xffffffffu, ss, 4);
        float inv = 1.0f / fmaxf(sqrtf(ss), 1e-12f);

        int node = node0 + ty * 4 + i;
        if (node < N_NODES) {
            out4[(size_t)node * 16 + tx] =
                make_float4(a[0] * inv, a[1] * inv, a[2] * inv, a[3] * inv);
            out4[(size_t)node * 16 + 8 + tx] =
                make_float4(a[4] * inv, a[5] * inv, a[6] * inv, a[7] * inv);
        }
    }
}

// ---------------------------------------------------------------------------
// inputs: 0 features[50000,64] f32  1 edge_src[800000] i32  2 edge_dst i32
//         3 edge_weight f32         4 W[64,128] f32         5 b[64] f32
// ---------------------------------------------------------------------------
extern "C" void kernel_launch(void* const* d_in, const int* in_sizes, int n_in,
                              void* d_out, int out_size) {
    const float4* feat4 = (const float4*)d_in[0];
    const int*    esrc  = (const int*)d_in[1];
    const int*    edst  = (const int*)d_in[2];
    const float*  ew    = (const float*)d_in[3];
    const float*  W     = (const float*)d_in[4];
    const float*  bias  = (const float*)d_in[5];
    float4*       out4  = (float4*)d_out;

    cudaFuncSetAttribute(gemm_norm_kernel,
                         cudaFuncAttributeMaxDynamicSharedMemorySize, GEMM_SMEM);

    int4* rank4;
    cudaGetSymbolAddress((void**)&rank4, g_rank);

    conv_hist_kernel<<<(N_NODES * 8 + 255) / 256, 256>>>(
        feat4, (const int4*)edst, rank4);
    scan_kernel<<<SCAN_BLOCKS, 256>>>();
    fill_kernel<<<(N_EDGES / 4 + 255) / 256, 256>>>(
        (const int4*)esrc, (const int4*)edst, (const float4*)ew,
        (const int4*)rank4);
    {
        long long threads = (long long)N_NODES * 32;
        gather_kernel<<<(int)((threads + 255) / 256), 256>>>();
    }
    gemm_norm_kernel<<<N_TILES, 256, GEMM_SMEM>>>(feat4, W, bias, out4);

    (void)in_sizes; (void)n_in; (void)out_size;
}

// round 8
// speedup vs baseline: 1.0858x; 1.0858x over previous
#include <cuda_runtime.h>
#include <cuda_fp16.h>

#define N_NODES 50000
#define N_EDGES 800000
#define D 64
#define SCAN_BLOCKS 196
#define N_TILES 391              // ceil(50000/128)

// ---------------- scratch (device globals; no allocs allowed) ----------------
// Mutable state is zero at process start (static init) and re-zeroed by
// fill_kernel each replay, so every graph replay sees identical initial state.
__device__ int                g_deg[N_NODES];
__device__ int                g_start[N_NODES + 1];
__device__ int                g_rank[N_EDGES];
__device__ unsigned long long g_blk_pack[256];        // (flag<<32)|value
__device__ int2               g_edges[N_EDGES];       // (src, weight) grouped by dst
__device__ uint4              g_featH4[N_NODES * 8];  // fp16 features, 8 halves/uint4
__device__ float4             g_neighbor[N_NODES * 16];

// ---------------------------------------------------------------------------
// K1: fp32->fp16 feature convert + rank-capturing destination histogram.
// ---------------------------------------------------------------------------
__global__ void conv_hist_kernel(const float4* __restrict__ feat4,
                                 const int4*   __restrict__ edst4,
                                 int4*         __restrict__ rank4) {
    int i = blockIdx.x * blockDim.x + threadIdx.x;
    if (i < N_NODES * 8) {
        float4 a = __ldg(feat4 + (size_t)i * 2);
        float4 b = __ldg(feat4 + (size_t)i * 2 + 1);
        uint4 o;
        *(__half2*)&o.x = __floats2half2_rn(a.x, a.y);
        *(__half2*)&o.y = __floats2half2_rn(a.z, a.w);
        *(__half2*)&o.z = __floats2half2_rn(b.x, b.y);
        *(__half2*)&o.w = __floats2half2_rn(b.z, b.w);
        g_featH4[i] = o;
    }
    if (i < N_EDGES / 4) {
        int4 d = __ldg(edst4 + i);
        int4 r;
        r.x = atomicAdd(&g_deg[d.x], 1);
        r.y = atomicAdd(&g_deg[d.y], 1);
        r.z = atomicAdd(&g_deg[d.z], 1);
        r.w = atomicAdd(&g_deg[d.w], 1);
        rank4[i] = r;
    }
}

// ---------------------------------------------------------------------------
// K2: single-pass exclusive scan (decoupled lookback), 196 blocks x 256
// ---------------------------------------------------------------------------
__device__ __forceinline__ int block_incl_scan_256(int v, int t, int* warp_sums) {
    int x = v;
#pragma unroll
    for (int off = 1; off < 32; off <<= 1) {
        int y = __shfl_up_sync(0xffffffffu, x, off);
        if ((t & 31) >= off) x += y;
    }
    if ((t & 31) == 31) warp_sums[t >> 5] = x;
    __syncthreads();
    if (t < 8) {
        int s = warp_sums[t];
#pragma unroll
        for (int off = 1; off < 8; off <<= 1) {
            int y = __shfl_up_sync(0x000000ffu, s, off);
            if (t >= off) s += y;
        }
        warp_sums[t] = s;
    }
    __syncthreads();
    if (t >= 32) x += warp_sums[(t >> 5) - 1];
    return x;
}

__global__ void scan_kernel() {
    __shared__ int warp_sums[8];
    __shared__ int s_agg;
    __shared__ int s_excl;
    int t = threadIdx.x, bid = blockIdx.x;
    int i = bid * 256 + t;

    int v = (i < N_NODES) ? g_deg[i] : 0;
    int incl = block_incl_scan_256(v, t, warp_sums);
    if (t == 255) s_agg = incl;
    __syncthreads();
    int agg = s_agg;

    if (t == 0) {
        unsigned long long p = (bid == 0)
            ? ((2ULL << 32) | (unsigned)agg)
            : ((1ULL << 32) | (unsigned)agg);
        atomicExch(&g_blk_pack[bid], p);
        if (bid == 0) s_excl = 0;
    }
    if (bid > 0 && t < 32) {
        int excl = 0;
        int look = bid - 1;
        while (true) {
            int idx = look - t;
            unsigned long long pk = (idx >= 0) ? atomicAdd(&g_blk_pack[idx], 0ULL)
                                               : (2ULL << 32);
            int f   = (int)(pk >> 32);
            int val = (int)(pk & 0xffffffffULL);
            unsigned ready = __ballot_sync(0xffffffffu, f >= 1);
            if (ready != 0xffffffffu) continue;
            unsigned pre = __ballot_sync(0xffffffffu, f == 2);
            if (pre) {
                int firstp = __ffs(pre) - 1;
                int contrib = (t <= firstp) ? val : 0;
#pragma unroll
                for (int o = 16; o; o >>= 1) contrib += __shfl_xor_sync(0xffffffffu, contrib, o);
                excl += contrib;
                break;
            } else {
                int contrib = val;
#pragma unroll
                for (int o = 16; o; o >>= 1) contrib += __shfl_xor_sync(0xffffffffu, contrib, o);
                excl += contrib;
                look -= 32;
            }
        }
        if (t == 0) {
            atomicExch(&g_blk_pack[bid], (2ULL << 32) | (unsigned)(excl + agg));
            s_excl = excl;
        }
    }
    __syncthreads();
    int base = s_excl;
    if (i < N_NODES) g_start[i] = base + incl - v;
    if (i == 0) g_start[N_NODES] = N_EDGES;
}

// ---------------------------------------------------------------------------
// K3: atomic-free CSR fill (slot = g_start[dst] + rank) + state re-zero.
// ---------------------------------------------------------------------------
__global__ void fill_kernel(const int4*   __restrict__ esrc4,
                            const int4*   __restrict__ edst4,
                            const float4* __restrict__ ew4,
                            const int4*   __restrict__ rank4) {
    int i = blockIdx.x * blockDim.x + threadIdx.x;
    if (i < N_EDGES / 4) {
        int4   s = __ldg(esrc4 + i);
        int4   d = __ldg(edst4 + i);
        float4 w = __ldg(ew4 + i);
        int4   r = __ldg(rank4 + i);
        g_edges[g_start[d.x] + r.x] = make_int2(s.x, __float_as_int(w.x));
        g_edges[g_start[d.y] + r.y] = make_int2(s.y, __float_as_int(w.y));
        g_edges[g_start[d.z] + r.z] = make_int2(s.z, __float_as_int(w.z));
        g_edges[g_start[d.w] + r.w] = make_int2(s.w, __float_as_int(w.w));
    }
    if (i < N_NODES) g_deg[i] = 0;
    if (i < 256) g_blk_pack[i] = 0ULL;
}

// ---------------------------------------------------------------------------
// K4: gather, 8 lanes/node, x8 predicated batch (16 loads in flight/thread,
// no serial tail). OOB edges load row 0 with weight 0 (harmless, L1-hit).
// ---------------------------------------------------------------------------
__global__ __launch_bounds__(256)
void gather_kernel() {
    int t = blockIdx.x * blockDim.x + threadIdx.x;
    int n    = t >> 3;
    int lane = t & 7;
    if (n >= N_NODES) return;

    int j0 = g_start[n];
    int j1 = g_start[n + 1];

    float a[8] = {0.f, 0.f, 0.f, 0.f, 0.f, 0.f, 0.f, 0.f};

    for (int j = j0; j < j1; j += 8) {
        int2 r[8];
#pragma unroll
        for (int e = 0; e < 8; e++) {
            int jj = j + e;
            r[e] = (jj < j1) ? __ldg(&g_edges[jj]) : make_int2(0, 0);
        }
#pragma unroll
        for (int e = 0; e < 8; e++) {
            uint4 h = __ldg(&g_featH4[(size_t)r[e].x * 8 + lane]);
            float w = __int_as_float(r[e].y);
            float2 p0 = __half22float2(*(__half2*)&h.x);
            float2 p1 = __half22float2(*(__half2*)&h.y);
            float2 p2 = __half22float2(*(__half2*)&h.z);
            float2 p3 = __half22float2(*(__half2*)&h.w);
            a[0] += w * p0.x; a[1] += w * p0.y;
            a[2] += w * p1.x; a[3] += w * p1.y;
            a[4] += w * p2.x; a[5] += w * p2.y;
            a[6] += w * p3.x; a[7] += w * p3.y;
        }
    }

    g_neighbor[(size_t)n * 16 + lane * 2]     = make_float4(a[0], a[1], a[2], a[3]);
    g_neighbor[(size_t)n * 16 + lane * 2 + 1] = make_float4(a[4], a[5], a[6], a[7]);
}

// ---------------------------------------------------------------------------
// K5: GEMM + bias + L2-normalize, k-split staging for 3 blocks/SM.
// 391 blocks x 256 threads, 128-node tile each (single wave at occ 3).
// ---------------------------------------------------------------------------
#define XP 68
#define WP 68
#define GEMM_SMEM ((128 * XP + 128 * WP) * 4)

#define FFMA2(acc, a, b) \
    asm("fma.rn.f32x2 %0, %1, %2, %0;" : "+l"(acc) : "l"(a), "l"(b))
#define PACK2(dst, lo, hi) \
    asm("mov.b64 %0, {%1, %2};" : "=l"(dst) : "f"(lo), "f"(hi))
#define UNPACK2(lo, hi, src) \
    asm("mov.b64 {%0, %1}, %2;" : "=f"(lo), "=f"(hi) : "l"(src))

__global__ __launch_bounds__(256, 3)
void gemm_norm_kernel(const float4* __restrict__ feat4,
                      const float*  __restrict__ W,
                      const float*  __restrict__ bias,
                      float4*       __restrict__ out4) {
    extern __shared__ float sm[];
    float* xs = sm;              // [128 nodes][XP]  (one 64-k half at a time)
    float* ws = sm + 128 * XP;   // [128 k][WP]

    int t = threadIdx.x;
    int tx = t & 7;
    int ty = t >> 3;
    int node0 = blockIdx.x * 128;

    // W[o][k] (64x128 row-major) -> ws[k][o]
    for (int i = t; i < 64 * 128; i += 256) {
        int o = i >> 7, k = i & 127;
        ws[k * WP + o] = __ldg(W + i);
    }

    unsigned long long acc[4][4];
    {
        float4 bA = *reinterpret_cast<const float4*>(bias + 4 * tx);
        float4 bB = *reinterpret_cast<const float4*>(bias + 32 + 4 * tx);
        unsigned long long b0, b1, b2, b3;
        PACK2(b0, bA.x, bA.y); PACK2(b1, bA.z, bA.w);
        PACK2(b2, bB.x, bB.y); PACK2(b3, bB.z, bB.w);
#pragma unroll
        for (int i = 0; i < 4; i++) {
            acc[i][0] = b0; acc[i][1] = b1; acc[i][2] = b2; acc[i][3] = b3;
        }
    }

#pragma unroll
    for (int half = 0; half < 2; half++) {
        const float4* src = (half == 0) ? feat4 : g_neighbor;
        __syncthreads();   // previous half's reads done before overwrite
        for (int idx = t; idx < 128 * 16; idx += 256) {
            int n = idx >> 4, q = idx & 15;
            int node = node0 + n;
            float4 v = make_float4(0.f, 0.f, 0.f, 0.f);
            if (node < N_NODES) v = __ldg(src + (size_t)node * 16 + q);
            *reinterpret_cast<float4*>(xs + n * XP + q * 4) = v;
        }
        __syncthreads();

        const float* xrow = xs + ty * 4 * XP;
        const float* wsh  = ws + half * 64 * WP;
#pragma unroll 4
        for (int k = 0; k < 64; k++) {
            float4 wA = *reinterpret_cast<const float4*>(wsh + k * WP + 4 * tx);
            float4 wB = *reinterpret_cast<const float4*>(wsh + k * WP + 32 + 4 * tx);
            unsigned long long w0, w1, w2, w3;
            PACK2(w0, wA.x, wA.y); PACK2(w1, wA.z, wA.w);
            PACK2(w2, wB.x, wB.y); PACK2(w3, wB.z, wB.w);
#pragma unroll
            for (int i = 0; i < 4; i++) {
                float x = xrow[i * XP + k];
                unsigned long long xx;
                asm("mov.b64 %0, {%1, %1};" : "=l"(xx) : "f"(x));
                FFMA2(acc[i][0], xx, w0);
                FFMA2(acc[i][1], xx, w1);
                FFMA2(acc[i][2], xx, w2);
                FFMA2(acc[i][3], xx, w3);
            }
        }
    }

#pragma unroll
    for (int i = 0; i < 4; i++) {
        float a[8];
        UNPACK2(a[0], a[1], acc[i][0]);
        UNPACK2(a[2], a[3], acc[i][1]);
        UNPACK2(a[4], a[5], acc[i][2]);
        UNPACK2(a[6], a[7], acc[i][3]);
        float ss = 0.f;
#pragma unroll
        for (int j = 0; j < 8; j++) ss += a[j] * a[j];
        ss += __shfl_xor_sync(0xffffffffu, ss, 1);
        ss += __shfl_xor_sync(0xffffffffu, ss, 2);
        ss += __shfl_xor_sync(0xffffffffu, ss, 4);
        float inv = 1.0f / fmaxf(sqrtf(ss), 1e-12f);

        int node = node0 + ty * 4 + i;
        if (node < N_NODES) {
            out4[(size_t)node * 16 + tx] =
                make_float4(a[0] * inv, a[1] * inv, a[2] * inv, a[3] * inv);
            out4[(size_t)node * 16 + 8 + tx] =
                make_float4(a[4] * inv, a[5] * inv, a[6] * inv, a[7] * inv);
        }
    }
}

// ---------------------------------------------------------------------------
// inputs: 0 features[50000,64] f32  1 edge_src[800000] i32  2 edge_dst i32
//         3 edge_weight f32         4 W[64,128] f32         5 b[64] f32
// ---------------------------------------------------------------------------
extern "C" void kernel_launch(void* const* d_in, const int* in_sizes, int n_in,
                              void* d_out, int out_size) {
    const float4* feat4 = (const float4*)d_in[0];
    const int*    esrc  = (const int*)d_in[1];
    const int*    edst  = (const int*)d_in[2];
    const float*  ew    = (const float*)d_in[3];
    const float*  W     = (const float*)d_in[4];
    const float*  bias  = (const float*)d_in[5];
    float4*       out4  = (float4*)d_out;

    cudaFuncSetAttribute(gemm_norm_kernel,
                         cudaFuncAttributeMaxDynamicSharedMemorySize, GEMM_SMEM);

    int4* rank4;
    cudaGetSymbolAddress((void**)&rank4, g_rank);

    conv_hist_kernel<<<(N_NODES * 8 + 255) / 256, 256>>>(
        feat4, (const int4*)edst, rank4);
    scan_kernel<<<SCAN_BLOCKS, 256>>>();
    fill_kernel<<<(N_EDGES / 4 + 255) / 256, 256>>>(
        (const int4*)esrc, (const int4*)edst, (const float4*)ew,
        (const int4*)rank4);
    {
        long long threads = (long long)N_NODES * 8;
        gather_kernel<<<(int)((threads + 255) / 256), 256>>>();
    }
    gemm_norm_kernel<<<N_TILES, 256, GEMM_SMEM>>>(feat4, W, bias, out4);

    (void)in_sizes; (void)n_in; (void)out_size;
}

// round 10
// speedup vs baseline: 1.3023x; 1.1994x over previous
#include <cuda_runtime.h>
#include <cuda_fp16.h>

#define N_NODES 50000
#define N_EDGES 800000
#define D 64
#define SCAN_BLOCKS 196
#define N_TILES 391              // ceil(50000/128)

// ---------------- scratch (device globals; no allocs allowed) ----------------
// Mutable state is zero at process start (static init) and re-zeroed by
// fill_kernel each replay, so every graph replay sees identical initial state.
__device__ int                g_deg[N_NODES];
__device__ int                g_start[N_NODES + 1];
__device__ int                g_rank[N_EDGES];
__device__ unsigned long long g_blk_pack[256];        // (flag<<32)|value
__device__ int2               g_edges[N_EDGES];       // (src, weight) grouped by dst
__device__ float4             g_Y1[N_NODES * 16];     // F@W1^T + b   (fp32)
__device__ uint4              g_Y2h[N_NODES * 8];     // F@W2^T as fp16, 8 halves/uint4

// ---------------------------------------------------------------------------
// K1 (side stream): histogram of edge destinations, rank-capturing.
// ---------------------------------------------------------------------------
__global__ void hist_kernel(const int4* __restrict__ edst4,
                            int4*       __restrict__ rank4) {
    int i = blockIdx.x * blockDim.x + threadIdx.x;
    if (i < N_EDGES / 4) {
        int4 d = __ldg(edst4 + i);
        int4 r;
        r.x = atomicAdd(&g_deg[d.x], 1);
        r.y = atomicAdd(&g_deg[d.y], 1);
        r.z = atomicAdd(&g_deg[d.z], 1);
        r.w = atomicAdd(&g_deg[d.w], 1);
        rank4[i] = r;
    }
}

// ---------------------------------------------------------------------------
// K2 (side stream): single-pass exclusive scan (decoupled lookback)
// ---------------------------------------------------------------------------
__device__ __forceinline__ int block_incl_scan_256(int v, int t, int* warp_sums) {
    int x = v;
#pragma unroll
    for (int off = 1; off < 32; off <<= 1) {
        int y = __shfl_up_sync(0xffffffffu, x, off);
        if ((t & 31) >= off) x += y;
    }
    if ((t & 31) == 31) warp_sums[t >> 5] = x;
    __syncthreads();
    if (t < 8) {
        int s = warp_sums[t];
#pragma unroll
        for (int off = 1; off < 8; off <<= 1) {
            int y = __shfl_up_sync(0x000000ffu, s, off);
            if (t >= off) s += y;
        }
        warp_sums[t] = s;
    }
    __syncthreads();
    if (t >= 32) x += warp_sums[(t >> 5) - 1];
    return x;
}

__global__ void scan_kernel() {
    __shared__ int warp_sums[8];
    __shared__ int s_agg;
    __shared__ int s_excl;
    int t = threadIdx.x, bid = blockIdx.x;
    int i = bid * 256 + t;

    int v = (i < N_NODES) ? g_deg[i] : 0;
    int incl = block_incl_scan_256(v, t, warp_sums);
    if (t == 255) s_agg = incl;
    __syncthreads();
    int agg = s_agg;

    if (t == 0) {
        unsigned long long p = (bid == 0)
            ? ((2ULL << 32) | (unsigned)agg)
            : ((1ULL << 32) | (unsigned)agg);
        atomicExch(&g_blk_pack[bid], p);
        if (bid == 0) s_excl = 0;
    }
    if (bid > 0 && t < 32) {
        int excl = 0;
        int look = bid - 1;
        while (true) {
            int idx = look - t;
            unsigned long long pk = (idx >= 0) ? atomicAdd(&g_blk_pack[idx], 0ULL)
                                               : (2ULL << 32);
            int f   = (int)(pk >> 32);
            int val = (int)(pk & 0xffffffffULL);
            unsigned ready = __ballot_sync(0xffffffffu, f >= 1);
            if (ready != 0xffffffffu) continue;
            unsigned pre = __ballot_sync(0xffffffffu, f == 2);
            if (pre) {
                int firstp = __ffs(pre) - 1;
                int contrib = (t <= firstp) ? val : 0;
#pragma unroll
                for (int o = 16; o; o >>= 1) contrib += __shfl_xor_sync(0xffffffffu, contrib, o);
                excl += contrib;
                break;
            } else {
                int contrib = val;
#pragma unroll
                for (int o = 16; o; o >>= 1) contrib += __shfl_xor_sync(0xffffffffu, contrib, o);
                excl += contrib;
                look -= 32;
            }
        }
        if (t == 0) {
            atomicExch(&g_blk_pack[bid], (2ULL << 32) | (unsigned)(excl + agg));
            s_excl = excl;
        }
    }
    __syncthreads();
    int base = s_excl;
    if (i < N_NODES) g_start[i] = base + incl - v;
    if (i == 0) g_start[N_NODES] = N_EDGES;
}

// ---------------------------------------------------------------------------
// K3 (side stream): atomic-free CSR fill + state re-zero for next replay.
// ---------------------------------------------------------------------------
__global__ void fill_kernel(const int4*   __restrict__ esrc4,
                            const int4*   __restrict__ edst4,
                            const float4* __restrict__ ew4,
                            const int4*   __restrict__ rank4) {
    int i = blockIdx.x * blockDim.x + threadIdx.x;
    if (i < N_EDGES / 4) {
        int4   s = __ldg(esrc4 + i);
        int4   d = __ldg(edst4 + i);
        float4 w = __ldg(ew4 + i);
        int4   r = __ldg(rank4 + i);
        g_edges[g_start[d.x] + r.x] = make_int2(s.x, __float_as_int(w.x));
        g_edges[g_start[d.y] + r.y] = make_int2(s.y, __float_as_int(w.y));
        g_edges[g_start[d.z] + r.z] = make_int2(s.z, __float_as_int(w.z));
        g_edges[g_start[d.w] + r.w] = make_int2(s.w, __float_as_int(w.w));
    }
    if (i < N_NODES) g_deg[i] = 0;
    if (i < 256) g_blk_pack[i] = 0ULL;
}

// ---------------------------------------------------------------------------
// K4 (main stream, concurrent with K1-K3):
//   pass 0: Y1 = F @ W1^T + b  -> g_Y1 (fp32)   [W cols 0..63]
//   pass 1: Y2 = F @ W2^T      -> g_Y2h (fp16)  [W cols 64..127]
// 391 blocks x 256 threads, 128-node tile; x staged once, two 64-k register
// passes. 34.8KB xs + 34.8KB ws -> occ 3, single wave. fma.rn.f32x2.
// ---------------------------------------------------------------------------
#define XP 68
#define WP 68
#define GEMM_SMEM ((128 * XP + 128 * WP) * 4)

#define FFMA2(acc, a, b) \
    asm("fma.rn.f32x2 %0, %1, %2, %0;" : "+l"(acc) : "l"(a), "l"(b))
#define PACK2(dst, lo, hi) \
    asm("mov.b64 %0, {%1, %2};" : "=l"(dst) : "f"(lo), "f"(hi))
#define UNPACK2(lo, hi, src) \
    asm("mov.b64 {%0, %1}, %2;" : "=f"(lo), "=f"(hi) : "l"(src))

__global__ __launch_bounds__(256, 3)
void gemm1_kernel(const float4* __restrict__ feat4,
                  const float*  __restrict__ W,
                  const float*  __restrict__ bias) {
    extern __shared__ float sm[];
    float* xs = sm;              // [128 nodes][XP], features only
    float* ws = sm + 128 * XP;   // [128 k][WP], both W halves

    int t = threadIdx.x;
    int tx = t & 7;
    int ty = t >> 3;
    int node0 = blockIdx.x * 128;

    // W[o][kk] (64x128 row-major) -> ws[kk][o]
    for (int i = t; i < 64 * 128; i += 256) {
        int o = i >> 7, kk = i & 127;
        ws[kk * WP + o] = __ldg(W + i);
    }
    // features -> xs
    for (int idx = t; idx < 128 * 16; idx += 256) {
        int n = idx >> 4, q = idx & 15;
        int node = node0 + n;
        float4 v = make_float4(0.f, 0.f, 0.f, 0.f);
        if (node < N_NODES) v = __ldg(feat4 + (size_t)node * 16 + q);
        *reinterpret_cast<float4*>(xs + n * XP + q * 4) = v;
    }
    __syncthreads();

    const float* xrow = xs + ty * 4 * XP;
    unsigned long long acc[4][4];

#pragma unroll
    for (int pass = 0; pass < 2; pass++) {
        // init accumulators: bias for Y1 pass, zero for Y2 pass
        if (pass == 0) {
            float4 bA = *reinterpret_cast<const float4*>(bias + 4 * tx);
            float4 bB = *reinterpret_cast<const float4*>(bias + 32 + 4 * tx);
            unsigned long long b0, b1, b2, b3;
            PACK2(b0, bA.x, bA.y); PACK2(b1, bA.z, bA.w);
            PACK2(b2, bB.x, bB.y); PACK2(b3, bB.z, bB.w);
#pragma unroll
            for (int i = 0; i < 4; i++) {
                acc[i][0] = b0; acc[i][1] = b1; acc[i][2] = b2; acc[i][3] = b3;
            }
        } else {
#pragma unroll
            for (int i = 0; i < 4; i++)
                acc[i][0] = acc[i][1] = acc[i][2] = acc[i][3] = 0ULL;
        }

        const float* wsh = ws + pass * 64 * WP;
#pragma unroll 4
        for (int k = 0; k < 64; k++) {
            float4 wA = *reinterpret_cast<const float4*>(wsh + k * WP + 4 * tx);
            float4 wB = *reinterpret_cast<const float4*>(wsh + k * WP + 32 + 4 * tx);
            unsigned long long w0, w1, w2, w3;
            PACK2(w0, wA.x, wA.y); PACK2(w1, wA.z, wA.w);
            PACK2(w2, wB.x, wB.y); PACK2(w3, wB.z, wB.w);
#pragma unroll
            for (int i = 0; i < 4; i++) {
                float x = xrow[i * XP + k];
                unsigned long long xx;
                asm("mov.b64 %0, {%1, %1};" : "=l"(xx) : "f"(x));
                FFMA2(acc[i][0], xx, w0);
                FFMA2(acc[i][1], xx, w1);
                FFMA2(acc[i][2], xx, w2);
                FFMA2(acc[i][3], xx, w3);
            }
        }

        // epilogue: pass 0 -> fp32 Y1; pass 1 -> fp16 Y2h
#pragma unroll
        for (int i = 0; i < 4; i++) {
            int node = node0 + ty * 4 + i;
            if (node >= N_NODES) continue;
            float a[8];
            UNPACK2(a[0], a[1], acc[i][0]);
            UNPACK2(a[2], a[3], acc[i][1]);
            UNPACK2(a[4], a[5], acc[i][2]);
            UNPACK2(a[6], a[7], acc[i][3]);
            if (pass == 0) {
                g_Y1[(size_t)node * 16 + tx]     = make_float4(a[0], a[1], a[2], a[3]);
                g_Y1[(size_t)node * 16 + 8 + tx] = make_float4(a[4], a[5], a[6], a[7]);
            } else {
                uint2* y2h = reinterpret_cast<uint2*>(g_Y2h);
                uint2 pA, pB;
                *(__half2*)&pA.x = __floats2half2_rn(a[0], a[1]);
                *(__half2*)&pA.y = __floats2half2_rn(a[2], a[3]);
                *(__half2*)&pB.x = __floats2half2_rn(a[4], a[5]);
                *(__half2*)&pB.y = __floats2half2_rn(a[6], a[7]);
                y2h[(size_t)node * 16 + tx]     = pA;
                y2h[(size_t)node * 16 + 8 + tx] = pB;
            }
        }
    }
}

// ---------------------------------------------------------------------------
// K5 (join): gather over Y2h + Y1 add + L2 normalize -> final out.
// 8 lanes/node, x8 predicated batch (16 loads in flight, no serial tail).
// OOB edges load row 0 with weight 0 (harmless, L1-hit).
// ---------------------------------------------------------------------------
__global__ __launch_bounds__(256)
void gather2_kernel(float4* __restrict__ out4) {
    int t = blockIdx.x * blockDim.x + threadIdx.x;
    int n    = t >> 3;
    int lane = t & 7;
    if (n >= N_NODES) return;

    int j0 = g_start[n];
    int j1 = g_start[n + 1];

    float a[8] = {0.f, 0.f, 0.f, 0.f, 0.f, 0.f, 0.f, 0.f};

    for (int j = j0; j < j1; j += 8) {
        int2 r[8];
#pragma unroll
        for (int e = 0; e < 8; e++) {
            int jj = j + e;
            r[e] = (jj < j1) ? __ldg(&g_edges[jj]) : make_int2(0, 0);
        }
#pragma unroll
        for (int e = 0; e < 8; e++) {
            uint4 h = __ldg(&g_Y2h[(size_t)r[e].x * 8 + lane]);
            float w = __int_as_float(r[e].y);
            float2 p0 = __half22float2(*(__half2*)&h.x);
            float2 p1 = __half22float2(*(__half2*)&h.y);
            float2 p2 = __half22float2(*(__half2*)&h.z);
            float2 p3 = __half22float2(*(__half2*)&h.w);
            a[0] += w * p0.x; a[1] += w * p0.y;
            a[2] += w * p1.x; a[3] += w * p1.y;
            a[4] += w * p2.x; a[5] += w * p2.y;
            a[6] += w * p3.x; a[7] += w * p3.y;
        }
    }

    // add Y1 (includes bias), normalize across the node's 64 outputs
    float4 y1a = g_Y1[(size_t)n * 16 + lane * 2];
    float4 y1b = g_Y1[(size_t)n * 16 + lane * 2 + 1];
    a[0] += y1a.x; a[1] += y1a.y; a[2] += y1a.z; a[3] += y1a.w;
    a[4] += y1b.x; a[5] += y1b.y; a[6] += y1b.z; a[7] += y1b.w;

    float ss = 0.f;
#pragma unroll
    for (int i = 0; i < 8; i++) ss += a[i] * a[i];
    ss += __shfl_xor_sync(0xffffffffu, ss, 1);
    ss += __shfl_xor_sync(0xffffffffu, ss, 2);
    ss += __shfl_xor_sync(0xffffffffu, ss, 4);
    float inv = 1.0f / fmaxf(sqrtf(ss), 1e-12f);

    out4[(size_t)n * 16 + lane * 2] =
        make_float4(a[0] * inv, a[1] * inv, a[2] * inv, a[3] * inv);
    out4[(size_t)n * 16 + lane * 2 + 1] =
        make_float4(a[4] * inv, a[5] * inv, a[6] * inv, a[7] * inv);
}

// ---------------------------------------------------------------------------
// Launch graph:
//   main:  [fork] -> gemm1 ----------------\
//   side:  hist -> scan -> fill -> [join] -> gather2
// Streams/events created once on first (correctness) call; captured work is
// identical on every call.
// inputs: 0 features[50000,64] f32  1 edge_src[800000] i32  2 edge_dst i32
//         3 edge_weight f32         4 W[64,128] f32         5 b[64] f32
// ---------------------------------------------------------------------------
extern "C" void kernel_launch(void* const* d_in, const int* in_sizes, int n_in,
                              void* d_out, int out_size) {
    const float4* feat4 = (const float4*)d_in[0];
    const int*    esrc  = (const int*)d_in[1];
    const int*    edst  = (const int*)d_in[2];
    const float*  ew    = (const float*)d_in[3];
    const float*  W     = (const float*)d_in[4];
    const float*  bias  = (const float*)d_in[5];
    float4*       out4  = (float4*)d_out;

    static cudaStream_t s2 = nullptr;
    static cudaEvent_t  evF = nullptr, evJ = nullptr;
    if (s2 == nullptr) {
        cudaStreamCreateWithFlags(&s2, cudaStreamNonBlocking);
        cudaEventCreateWithFlags(&evF, cudaEventDisableTiming);
        cudaEventCreateWithFlags(&evJ, cudaEventDisableTiming);
        cudaFuncSetAttribute(gemm1_kernel,
                             cudaFuncAttributeMaxDynamicSharedMemorySize, GEMM_SMEM);
    }

    int4* rank4;
    cudaGetSymbolAddress((void**)&rank4, g_rank);

    // fork side branch off the capture stream
    cudaEventRecord(evF, 0);
    cudaStreamWaitEvent(s2, evF, 0);

    // side: CSR build
    hist_kernel<<<(N_EDGES / 4 + 255) / 256, 256, 0, s2>>>((const int4*)edst, rank4);
    scan_kernel<<<SCAN_BLOCKS, 256, 0, s2>>>();
    fill_kernel<<<(N_EDGES / 4 + 255) / 256, 256, 0, s2>>>(
        (const int4*)esrc, (const int4*)edst, (const float4*)ew,
        (const int4*)rank4);
    cudaEventRecord(evJ, s2);

    // main: dense GEMM (concurrent with CSR build)
    gemm1_kernel<<<N_TILES, 256, GEMM_SMEM>>>(feat4, W, bias);

    // join, then terminal gather
    cudaStreamWaitEvent(0, evJ, 0);
    {
        long long threads = (long long)N_NODES * 8;
        gather2_kernel<<<(int)((threads + 255) / 256), 256>>>(out4);
    }

    (void)in_sizes; (void)n_in; (void)out_size;
}

// round 14
// speedup vs baseline: 1.4545x; 1.1169x over previous
#include <cuda_runtime.h>
#include <cuda_fp16.h>
#include <stdint.h>

#define N_NODES 50000
#define N_EDGES 800000
#define SCAN_BLOCKS 196
#define N_TILES 391              // ceil(50000/128)

// ---------------- scratch (device globals; no allocs allowed) ----------------
__device__ int                g_deg[N_NODES];
__device__ int                g_start[N_NODES + 1];
__device__ int                g_rank[N_EDGES];
__device__ unsigned long long g_blk_pack[256];        // (flag<<32)|value
__device__ int2               g_edges[N_EDGES];       // (src, weight) grouped by dst
__device__ uint4              g_featH4[N_NODES * 8];  // A: features fp16, 8 halves/uint4
__device__ uint4              g_Bh4[1024];            // B: [128 out][64 k] fp16
__device__ float4             g_Y1[N_NODES * 16];     // F@W1^T + b   (fp32)
__device__ uint4              g_Y2h[N_NODES * 8];     // F@W2^T as fp16

__device__ __forceinline__ uint32_t smem_u32(const void* p) {
    uint32_t a;
    asm("{ .reg .u64 t; cvta.to.shared.u64 t, %1; cvt.u32.u64 %0, t; }"
        : "=r"(a) : "l"(p));
    return a;
}

// ---------------------------------------------------------------------------
// K0 (main stream): fp16 convert of features (A) and build of B from W.
//   B[o][k] = W[o][k] (o<64) ; B[64+o][k] = W[o][64+k]
// ---------------------------------------------------------------------------
__global__ void prep_kernel(const float4* __restrict__ feat4,
                            const float*  __restrict__ W) {
    int i = blockIdx.x * blockDim.x + threadIdx.x;
    if (i < N_NODES * 8) {
        float4 a = __ldg(feat4 + (size_t)i * 2);
        float4 b = __ldg(feat4 + (size_t)i * 2 + 1);
        uint4 o;
        *(__half2*)&o.x = __floats2half2_rn(a.x, a.y);
        *(__half2*)&o.y = __floats2half2_rn(a.z, a.w);
        *(__half2*)&o.z = __floats2half2_rn(b.x, b.y);
        *(__half2*)&o.w = __floats2half2_rn(b.z, b.w);
        g_featH4[i] = o;
    }
    if (i < 1024) {   // uint4 i -> B row o2 = i>>3, k base = (i&7)*8
        int o2 = i >> 3;
        int kb = (i & 7) * 8;
        const float* wrow = W + (size_t)(o2 & 63) * 128 + (o2 >> 6) * 64 + kb;
        float4 a = __ldg((const float4*)wrow);
        float4 b = __ldg((const float4*)(wrow + 4));
        uint4 o;
        *(__half2*)&o.x = __floats2half2_rn(a.x, a.y);
        *(__half2*)&o.y = __floats2half2_rn(a.z, a.w);
        *(__half2*)&o.z = __floats2half2_rn(b.x, b.y);
        *(__half2*)&o.w = __floats2half2_rn(b.z, b.w);
        g_Bh4[i] = o;
    }
}

// ---------------------------------------------------------------------------
// K1 (side stream): rank-capturing destination histogram.
// ---------------------------------------------------------------------------
__global__ void hist_kernel(const int4* __restrict__ edst4,
                            int4*       __restrict__ rank4) {
    int i = blockIdx.x * blockDim.x + threadIdx.x;
    if (i < N_EDGES / 4) {
        int4 d = __ldg(edst4 + i);
        int4 r;
        r.x = atomicAdd(&g_deg[d.x], 1);
        r.y = atomicAdd(&g_deg[d.y], 1);
        r.z = atomicAdd(&g_deg[d.z], 1);
        r.w = atomicAdd(&g_deg[d.w], 1);
        rank4[i] = r;
    }
}

// ---------------------------------------------------------------------------
// K2 (side stream): single-pass exclusive scan (decoupled lookback)
// ---------------------------------------------------------------------------
__device__ __forceinline__ int block_incl_scan_256(int v, int t, int* warp_sums) {
    int x = v;
#pragma unroll
    for (int off = 1; off < 32; off <<= 1) {
        int y = __shfl_up_sync(0xffffffffu, x, off);
        if ((t & 31) >= off) x += y;
    }
    if ((t & 31) == 31) warp_sums[t >> 5] = x;
    __syncthreads();
    if (t < 8) {
        int s = warp_sums[t];
#pragma unroll
        for (int off = 1; off < 8; off <<= 1) {
            int y = __shfl_up_sync(0x000000ffu, s, off);
            if (t >= off) s += y;
        }
        warp_sums[t] = s;
    }
    __syncthreads();
    if (t >= 32) x += warp_sums[(t >> 5) - 1];
    return x;
}

__global__ void scan_kernel() {
    __shared__ int warp_sums[8];
    __shared__ int s_agg;
    __shared__ int s_excl;
    int t = threadIdx.x, bid = blockIdx.x;
    int i = bid * 256 + t;

    int v = (i < N_NODES) ? g_deg[i] : 0;
    int incl = block_incl_scan_256(v, t, warp_sums);
    if (t == 255) s_agg = incl;
    __syncthreads();
    int agg = s_agg;

    if (t == 0) {
        unsigned long long p = (bid == 0)
            ? ((2ULL << 32) | (unsigned)agg)
            : ((1ULL << 32) | (unsigned)agg);
        atomicExch(&g_blk_pack[bid], p);
        if (bid == 0) s_excl = 0;
    }
    if (bid > 0 && t < 32) {
        int excl = 0;
        int look = bid - 1;
        while (true) {
            int idx = look - t;
            unsigned long long pk = (idx >= 0) ? atomicAdd(&g_blk_pack[idx], 0ULL)
                                               : (2ULL << 32);
            int f   = (int)(pk >> 32);
            int val = (int)(pk & 0xffffffffULL);
            unsigned ready = __ballot_sync(0xffffffffu, f >= 1);
            if (ready != 0xffffffffu) continue;
            unsigned pre = __ballot_sync(0xffffffffu, f == 2);
            if (pre) {
                int firstp = __ffs(pre) - 1;
                int contrib = (t <= firstp) ? val : 0;
#pragma unroll
                for (int o = 16; o; o >>= 1) contrib += __shfl_xor_sync(0xffffffffu, contrib, o);
                excl += contrib;
                break;
            } else {
                int contrib = val;
#pragma unroll
                for (int o = 16; o; o >>= 1) contrib += __shfl_xor_sync(0xffffffffu, contrib, o);
                excl += contrib;
                look -= 32;
            }
        }
        if (t == 0) {
            atomicExch(&g_blk_pack[bid], (2ULL << 32) | (unsigned)(excl + agg));
            s_excl = excl;
        }
    }
    __syncthreads();
    int base = s_excl;
    if (i < N_NODES) g_start[i] = base + incl - v;
    if (i == 0) g_start[N_NODES] = N_EDGES;
}

// ---------------------------------------------------------------------------
// K3 (side stream): atomic-free CSR fill + state re-zero for next replay.
// ---------------------------------------------------------------------------
__global__ void fill_kernel(const int4*   __restrict__ esrc4,
                            const int4*   __restrict__ edst4,
                            const float4* __restrict__ ew4,
                            const int4*   __restrict__ rank4) {
    int i = blockIdx.x * blockDim.x + threadIdx.x;
    if (i < N_EDGES / 4) {
        int4   s = __ldg(esrc4 + i);
        int4   d = __ldg(edst4 + i);
        float4 w = __ldg(ew4 + i);
        int4   r = __ldg(rank4 + i);
        g_edges[g_start[d.x] + r.x] = make_int2(s.x, __float_as_int(w.x));
        g_edges[g_start[d.y] + r.y] = make_int2(s.y, __float_as_int(w.y));
        g_edges[g_start[d.z] + r.z] = make_int2(s.z, __float_as_int(w.z));
        g_edges[g_start[d.w] + r.w] = make_int2(s.w, __float_as_int(w.w));
    }
    if (i < N_NODES) g_deg[i] = 0;
    if (i < 256) g_blk_pack[i] = 0ULL;
}

// ---------------------------------------------------------------------------
// K4 (main stream): HMMA GEMM.  D[128,128] = A_tile[128,64] @ B[128,64]^T
// (M=128 nodes, N=128 = Y1|Y2, K=64, fp16 in / fp32 accum).
// 8 warps; warp w = rows 16w..16w+15 x all 128 cols; mma.m16n8k16 row.col.
// A,B in smem, 144B row pitch (stride = 36 words = 4 banks -> ldmatrix
// conflict-free, no swizzle). B stored [n][k] = col-major KxN for .col.
// ---------------------------------------------------------------------------
#define PITCHB 144   // bytes per 64-half row in smem

__global__ __launch_bounds__(256)
void hmma_kernel(const float* __restrict__ bias) {
    __shared__ __align__(16) char smA[128 * PITCHB];
    __shared__ __align__(16) char smB[128 * PITCHB];
    __shared__ float bias_s[64];

    int t = threadIdx.x;
    int w = t >> 5, l = t & 31;
    int node0 = blockIdx.x * 128;

    if (t < 64) bias_s[t] = __ldg(bias + t);

    // stage A (fp16 features): 1024 uint4 (row = i>>3, 16B seg u = i&7)
    for (int i = t; i < 1024; i += 256) {
        int row = i >> 3, u = i & 7;
        int node = node0 + row;
        uint4 v = make_uint4(0u, 0u, 0u, 0u);
        if (node < N_NODES) v = __ldg(&g_featH4[(size_t)node * 8 + u]);
        *(uint4*)(smA + row * PITCHB + u * 16) = v;
    }
    // stage B
    for (int i = t; i < 1024; i += 256) {
        int row = i >> 3, u = i & 7;
        uint4 v = __ldg(&g_Bh4[i]);
        *(uint4*)(smB + row * PITCHB + u * 16) = v;
    }
    __syncthreads();

    uint32_t smA32 = smem_u32(smA);
    uint32_t smB32 = smem_u32(smB);

    // per-lane ldmatrix base offsets
    uint32_t aBase = smA32
        + (uint32_t)((w * 16 + ((l >> 3) & 1) * 8 + (l & 7)) * PITCHB + (l >> 4) * 16);
    uint32_t bBase = smB32
        + (uint32_t)((l & 7) * PITCHB + ((l >> 3) & 1) * 16);

    float acc[16][4];
#pragma unroll
    for (int nt = 0; nt < 16; nt++)
#pragma unroll
        for (int q = 0; q < 4; q++) acc[nt][q] = 0.f;

#pragma unroll
    for (int ks = 0; ks < 4; ks++) {
        uint32_t a0, a1, a2, a3;
        asm volatile("ldmatrix.sync.aligned.m8n8.x4.shared.b16 {%0,%1,%2,%3}, [%4];"
                     : "=r"(a0), "=r"(a1), "=r"(a2), "=r"(a3)
                     : "r"(aBase + ks * 32));
#pragma unroll
        for (int nt = 0; nt < 16; nt++) {
            uint32_t b0, b1;
            asm volatile("ldmatrix.sync.aligned.m8n8.x2.shared.b16 {%0,%1}, [%2];"
                         : "=r"(b0), "=r"(b1)
                         : "r"(bBase + nt * (8 * PITCHB) + ks * 32));
            asm volatile(
                "mma.sync.aligned.m16n8k16.row.col.f32.f16.f16.f32 "
                "{%0,%1,%2,%3}, {%4,%5,%6,%7}, {%8,%9}, {%0,%1,%2,%3};"
                : "+f"(acc[nt][0]), "+f"(acc[nt][1]),
                  "+f"(acc[nt][2]), "+f"(acc[nt][3])
                : "r"(a0), "r"(a1), "r"(a2), "r"(a3), "r"(b0), "r"(b1));
        }
    }

    // epilogue: lane holds cols tig*2,tig*2+1 at rows gid and gid+8
    int gid = l >> 2, tig = l & 3;
    int nodeA = node0 + w * 16 + gid;
    int nodeB = nodeA + 8;
    bool vA = nodeA < N_NODES, vB = nodeB < N_NODES;
    float*    Y1f = reinterpret_cast<float*>(g_Y1);
    uint32_t* Y2u = reinterpret_cast<uint32_t*>(g_Y2h);

#pragma unroll
    for (int nt = 0; nt < 8; nt++) {          // cols 0..63 -> Y1 (+bias, fp32)
        int c = nt * 8 + tig * 2;
        float b0 = bias_s[c], b1 = bias_s[c + 1];
        if (vA) *(float2*)&Y1f[(size_t)nodeA * 64 + c] =
            make_float2(acc[nt][0] + b0, acc[nt][1] + b1);
        if (vB) *(float2*)&Y1f[(size_t)nodeB * 64 + c] =
            make_float2(acc[nt][2] + b0, acc[nt][3] + b1);
    }
#pragma unroll
    for (int nt = 8; nt < 16; nt++) {         // cols 64..127 -> Y2 (fp16)
        int c = (nt - 8) * 8 + tig * 2;
        if (vA) {
            __half2 h = __floats2half2_rn(acc[nt][0], acc[nt][1]);
            Y2u[(size_t)nodeA * 32 + (c >> 1)] = *(uint32_t*)&h;
        }
        if (vB) {
            __half2 h = __floats2half2_rn(acc[nt][2], acc[nt][3]);
            Y2u[(size_t)nodeB * 32 + (c >> 1)] = *(uint32_t*)&h;
        }
    }
}

// ---------------------------------------------------------------------------
// K5 (join): gather over Y2h + Y1 add + L2 normalize -> final out.
// 8 lanes/node, x8 predicated batch (16 loads in flight, no serial tail).
// ---------------------------------------------------------------------------
__global__ __launch_bounds__(256)
void gather2_kernel(float4* __restrict__ out4) {
    int t = blockIdx.x * blockDim.x + threadIdx.x;
    int n    = t >> 3;
    int lane = t & 7;
    if (n >= N_NODES) return;

    int j0 = g_start[n];
    int j1 = g_start[n + 1];

    float a[8] = {0.f, 0.f, 0.f, 0.f, 0.f, 0.f, 0.f, 0.f};

    for (int j = j0; j < j1; j += 8) {
        int2 r[8];
#pragma unroll
        for (int e = 0; e < 8; e++) {
            int jj = j + e;
            r[e] = (jj < j1) ? __ldg(&g_edges[jj]) : make_int2(0, 0);
        }
#pragma unroll
        for (int e = 0; e < 8; e++) {
            uint4 h = __ldg(&g_Y2h[(size_t)r[e].x * 8 + lane]);
            float w = __int_as_float(r[e].y);
            float2 p0 = __half22float2(*(__half2*)&h.x);
            float2 p1 = __half22float2(*(__half2*)&h.y);
            float2 p2 = __half22float2(*(__half2*)&h.z);
            float2 p3 = __half22float2(*(__half2*)&h.w);
            a[0] += w * p0.x; a[1] += w * p0.y;
            a[2] += w * p1.x; a[3] += w * p1.y;
            a[4] += w * p2.x; a[5] += w * p2.y;
            a[6] += w * p3.x; a[7] += w * p3.y;
        }
    }

    float4 y1a = g_Y1[(size_t)n * 16 + lane * 2];
    float4 y1b = g_Y1[(size_t)n * 16 + lane * 2 + 1];
    a[0] += y1a.x; a[1] += y1a.y; a[2] += y1a.z; a[3] += y1a.w;
    a[4] += y1b.x; a[5] += y1b.y; a[6] += y1b.z; a[7] += y1b.w;

    float ss = 0.f;
#pragma unroll
    for (int i = 0; i < 8; i++) ss += a[i] * a[i];
    ss += __shfl_xor_sync(0xffffffffu, ss, 1);
    ss += __shfl_xor_sync(0xffffffffu, ss, 2);
    ss += __shfl_xor_sync(0xffffffffu, ss, 4);
    float inv = 1.0f / fmaxf(sqrtf(ss), 1e-12f);

    out4[(size_t)n * 16 + lane * 2] =
        make_float4(a[0] * inv, a[1] * inv, a[2] * inv, a[3] * inv);
    out4[(size_t)n * 16 + lane * 2 + 1] =
        make_float4(a[4] * inv, a[5] * inv, a[6] * inv, a[7] * inv);
}

// ---------------------------------------------------------------------------
// Launch graph:
//   main:  [fork] -> prep -> hmma ---------\
//   side:  hist -> scan -> fill -> [join] -> gather2
// inputs: 0 features[50000,64] f32  1 edge_src[800000] i32  2 edge_dst i32
//         3 edge_weight f32         4 W[64,128] f32         5 b[64] f32
// ---------------------------------------------------------------------------
extern "C" void kernel_launch(void* const* d_in, const int* in_sizes, int n_in,
                              void* d_out, int out_size) {
    const float4* feat4 = (const float4*)d_in[0];
    const int*    esrc  = (const int*)d_in[1];
    const int*    edst  = (const int*)d_in[2];
    const float*  ew    = (const float*)d_in[3];
    const float*  W     = (const float*)d_in[4];
    const float*  bias  = (const float*)d_in[5];
    float4*       out4  = (float4*)d_out;

    static cudaStream_t s2 = nullptr;
    static cudaEvent_t  evF = nullptr, evJ = nullptr;
    if (s2 == nullptr) {
        cudaStreamCreateWithFlags(&s2, cudaStreamNonBlocking);
        cudaEventCreateWithFlags(&evF, cudaEventDisableTiming);
        cudaEventCreateWithFlags(&evJ, cudaEventDisableTiming);
    }

    int4* rank4;
    cudaGetSymbolAddress((void**)&rank4, g_rank);

    // fork side branch off the capture stream
    cudaEventRecord(evF, 0);
    cudaStreamWaitEvent(s2, evF, 0);

    // side: CSR build
    hist_kernel<<<(N_EDGES / 4 + 255) / 256, 256, 0, s2>>>((const int4*)edst, rank4);
    scan_kernel<<<SCAN_BLOCKS, 256, 0, s2>>>();
    fill_kernel<<<(N_EDGES / 4 + 255) / 256, 256, 0, s2>>>(
        (const int4*)esrc, (const int4*)edst, (const float4*)ew,
        (const int4*)rank4);
    cudaEventRecord(evJ, s2);

    // main: prep + HMMA GEMM (concurrent with CSR build)
    prep_kernel<<<(N_NODES * 8 + 255) / 256, 256>>>(feat4, W);
    hmma_kernel<<<N_TILES, 256>>>(bias);

    // join, then terminal gather
    cudaStreamWaitEvent(0, evJ, 0);
    {
        long long threads = (long long)N_NODES * 8;
        gather2_kernel<<<(int)((threads + 255) / 256), 256>>>(out4);
    }

    (void)in_sizes; (void)n_in; (void)out_size;
}

// round 15
// speedup vs baseline: 1.4785x; 1.0165x over previous
#include <cuda_runtime.h>
#include <cuda_fp16.h>
#include <stdint.h>

#define N_NODES 50000
#define N_EDGES 800000
#define SCAN_BLOCKS 196
#define N_TILES 391              // ceil(50000/128)

// ---------------- scratch (device globals; no allocs allowed) ----------------
__device__ int                g_deg[N_NODES];
__device__ int                g_start[N_NODES + 1];
__device__ int                g_rank[N_EDGES];
__device__ unsigned long long g_blk_pack[256];        // (flag<<32)|value
__device__ int2               g_edges[N_EDGES];       // (src, weight) grouped by dst
__device__ uint4              g_Bh4[1024];            // B: [128 out][64 k] fp16
__device__ float4             g_Y1[N_NODES * 16];     // F@W1^T + b   (fp32)
__device__ uint4              g_Y2h[N_NODES * 8];     // F@W2^T as fp16

__device__ __forceinline__ uint32_t smem_u32(const void* p) {
    uint32_t a;
    asm("{ .reg .u64 t; cvta.to.shared.u64 t, %1; cvt.u32.u64 %0, t; }"
        : "=r"(a) : "l"(p));
    return a;
}

// ---------------------------------------------------------------------------
// K0 (main stream, tiny): build fp16 B from W.
//   B[o][k] = W[o][k] (o<64) ; B[64+o][k] = W[o][64+k]
// ---------------------------------------------------------------------------
__global__ void prepB_kernel(const float* __restrict__ W) {
    int i = blockIdx.x * blockDim.x + threadIdx.x;
    if (i < 1024) {   // uint4 i -> B row o2 = i>>3, k base = (i&7)*8
        int o2 = i >> 3;
        int kb = (i & 7) * 8;
        const float* wrow = W + (size_t)(o2 & 63) * 128 + (o2 >> 6) * 64 + kb;
        float4 a = __ldg((const float4*)wrow);
        float4 b = __ldg((const float4*)(wrow + 4));
        uint4 o;
        *(__half2*)&o.x = __floats2half2_rn(a.x, a.y);
        *(__half2*)&o.y = __floats2half2_rn(a.z, a.w);
        *(__half2*)&o.z = __floats2half2_rn(b.x, b.y);
        *(__half2*)&o.w = __floats2half2_rn(b.z, b.w);
        g_Bh4[i] = o;
    }
}

// ---------------------------------------------------------------------------
// K1 (side stream): rank-capturing destination histogram.
// ---------------------------------------------------------------------------
__global__ void hist_kernel(const int4* __restrict__ edst4,
                            int4*       __restrict__ rank4) {
    int i = blockIdx.x * blockDim.x + threadIdx.x;
    if (i < N_EDGES / 4) {
        int4 d = __ldg(edst4 + i);
        int4 r;
        r.x = atomicAdd(&g_deg[d.x], 1);
        r.y = atomicAdd(&g_deg[d.y], 1);
        r.z = atomicAdd(&g_deg[d.z], 1);
        r.w = atomicAdd(&g_deg[d.w], 1);
        rank4[i] = r;
    }
}

// ---------------------------------------------------------------------------
// K2 (side stream): single-pass exclusive scan (decoupled lookback)
// ---------------------------------------------------------------------------
__device__ __forceinline__ int block_incl_scan_256(int v, int t, int* warp_sums) {
    int x = v;
#pragma unroll
    for (int off = 1; off < 32; off <<= 1) {
        int y = __shfl_up_sync(0xffffffffu, x, off);
        if ((t & 31) >= off) x += y;
    }
    if ((t & 31) == 31) warp_sums[t >> 5] = x;
    __syncthreads();
    if (t < 8) {
        int s = warp_sums[t];
#pragma unroll
        for (int off = 1; off < 8; off <<= 1) {
            int y = __shfl_up_sync(0x000000ffu, s, off);
            if (t >= off) s += y;
        }
        warp_sums[t] = s;
    }
    __syncthreads();
    if (t >= 32) x += warp_sums[(t >> 5) - 1];
    return x;
}

__global__ void scan_kernel() {
    __shared__ int warp_sums[8];
    __shared__ int s_agg;
    __shared__ int s_excl;
    int t = threadIdx.x, bid = blockIdx.x;
    int i = bid * 256 + t;

    int v = (i < N_NODES) ? g_deg[i] : 0;
    int incl = block_incl_scan_256(v, t, warp_sums);
    if (t == 255) s_agg = incl;
    __syncthreads();
    int agg = s_agg;

    if (t == 0) {
        unsigned long long p = (bid == 0)
            ? ((2ULL << 32) | (unsigned)agg)
            : ((1ULL << 32) | (unsigned)agg);
        atomicExch(&g_blk_pack[bid], p);
        if (bid == 0) s_excl = 0;
    }
    if (bid > 0 && t < 32) {
        int excl = 0;
        int look = bid - 1;
        while (true) {
            int idx = look - t;
            unsigned long long pk = (idx >= 0) ? atomicAdd(&g_blk_pack[idx], 0ULL)
                                               : (2ULL << 32);
            int f   = (int)(pk >> 32);
            int val = (int)(pk & 0xffffffffULL);
            unsigned ready = __ballot_sync(0xffffffffu, f >= 1);
            if (ready != 0xffffffffu) continue;
            unsigned pre = __ballot_sync(0xffffffffu, f == 2);
            if (pre) {
                int firstp = __ffs(pre) - 1;
                int contrib = (t <= firstp) ? val : 0;
#pragma unroll
                for (int o = 16; o; o >>= 1) contrib += __shfl_xor_sync(0xffffffffu, contrib, o);
                excl += contrib;
                break;
            } else {
                int contrib = val;
#pragma unroll
                for (int o = 16; o; o >>= 1) contrib += __shfl_xor_sync(0xffffffffu, contrib, o);
                excl += contrib;
                look -= 32;
            }
        }
        if (t == 0) {
            atomicExch(&g_blk_pack[bid], (2ULL << 32) | (unsigned)(excl + agg));
            s_excl = excl;
        }
    }
    __syncthreads();
    int base = s_excl;
    if (i < N_NODES) g_start[i] = base + incl - v;
    if (i == 0) g_start[N_NODES] = N_EDGES;
}

// ---------------------------------------------------------------------------
// K3 (side stream): atomic-free CSR fill + state re-zero for next replay.
// ---------------------------------------------------------------------------
__global__ void fill_kernel(const int4*   __restrict__ esrc4,
                            const int4*   __restrict__ edst4,
                            const float4* __restrict__ ew4,
                            const int4*   __restrict__ rank4) {
    int i = blockIdx.x * blockDim.x + threadIdx.x;
    if (i < N_EDGES / 4) {
        int4   s = __ldg(esrc4 + i);
        int4   d = __ldg(edst4 + i);
        float4 w = __ldg(ew4 + i);
        int4   r = __ldg(rank4 + i);
        g_edges[g_start[d.x] + r.x] = make_int2(s.x, __float_as_int(w.x));
        g_edges[g_start[d.y] + r.y] = make_int2(s.y, __float_as_int(w.y));
        g_edges[g_start[d.z] + r.z] = make_int2(s.z, __float_as_int(w.z));
        g_edges[g_start[d.w] + r.w] = make_int2(s.w, __float_as_int(w.w));
    }
    if (i < N_NODES) g_deg[i] = 0;
    if (i < 256) g_blk_pack[i] = 0ULL;
}

// ---------------------------------------------------------------------------
// K4 (main stream): HMMA GEMM.  D[128,128] = A_tile[128,64] @ B[128,64]^T
// (M=128 nodes, N=128 = Y1|Y2, K=64, fp16 in / fp32 accum).
// A staged directly from fp32 features (convert in-flight, no intermediate).
// 8 warps; warp w = rows 16w..16w+15 x all 128 cols; mma.m16n8k16 row.col.
// A,B in smem, 144B row pitch (conflict-free ldmatrix, no swizzle).
// ---------------------------------------------------------------------------
#define PITCHB 144   // bytes per 64-half row in smem

__global__ __launch_bounds__(256)
void hmma_kernel(const float4* __restrict__ feat4,
                 const float*  __restrict__ bias) {
    __shared__ __align__(16) char smA[128 * PITCHB];
    __shared__ __align__(16) char smB[128 * PITCHB];
    __shared__ float bias_s[64];

    int t = threadIdx.x;
    int w = t >> 5, l = t & 31;
    int node0 = blockIdx.x * 128;

    if (t < 64) bias_s[t] = __ldg(bias + t);

    // stage A: fp32 features -> fp16 smem (2048 float4, 8 per thread)
    for (int i = t; i < 2048; i += 256) {
        int row = i >> 4, u = i & 15;     // u = float4 index within row
        int node = node0 + row;
        float4 v = make_float4(0.f, 0.f, 0.f, 0.f);
        if (node < N_NODES) v = __ldg(feat4 + (size_t)node * 16 + u);
        uint2 h;
        *(__half2*)&h.x = __floats2half2_rn(v.x, v.y);
        *(__half2*)&h.y = __floats2half2_rn(v.z, v.w);
        *(uint2*)(smA + row * PITCHB + u * 8) = h;
    }
    // stage B (prebuilt fp16)
    for (int i = t; i < 1024; i += 256) {
        int row = i >> 3, u = i & 7;
        uint4 v = __ldg(&g_Bh4[i]);
        *(uint4*)(smB + row * PITCHB + u * 16) = v;
    }
    __syncthreads();

    uint32_t smA32 = smem_u32(smA);
    uint32_t smB32 = smem_u32(smB);

    uint32_t aBase = smA32
        + (uint32_t)((w * 16 + ((l >> 3) & 1) * 8 + (l & 7)) * PITCHB + (l >> 4) * 16);
    uint32_t bBase = smB32
        + (uint32_t)((l & 7) * PITCHB + ((l >> 3) & 1) * 16);

    float acc[16][4];
#pragma unroll
    for (int nt = 0; nt < 16; nt++)
#pragma unroll
        for (int q = 0; q < 4; q++) acc[nt][q] = 0.f;

#pragma unroll
    for (int ks = 0; ks < 4; ks++) {
        uint32_t a0, a1, a2, a3;
        asm volatile("ldmatrix.sync.aligned.m8n8.x4.shared.b16 {%0,%1,%2,%3}, [%4];"
                     : "=r"(a0), "=r"(a1), "=r"(a2), "=r"(a3)
                     : "r"(aBase + ks * 32));
#pragma unroll
        for (int nt = 0; nt < 16; nt++) {
            uint32_t b0, b1;
            asm volatile("ldmatrix.sync.aligned.m8n8.x2.shared.b16 {%0,%1}, [%2];"
                         : "=r"(b0), "=r"(b1)
                         : "r"(bBase + nt * (8 * PITCHB) + ks * 32));
            asm volatile(
                "mma.sync.aligned.m16n8k16.row.col.f32.f16.f16.f32 "
                "{%0,%1,%2,%3}, {%4,%5,%6,%7}, {%8,%9}, {%0,%1,%2,%3};"
                : "+f"(acc[nt][0]), "+f"(acc[nt][1]),
                  "+f"(acc[nt][2]), "+f"(acc[nt][3])
                : "r"(a0), "r"(a1), "r"(a2), "r"(a3), "r"(b0), "r"(b1));
        }
    }

    // epilogue: lane holds cols tig*2,tig*2+1 at rows gid and gid+8
    int gid = l >> 2, tig = l & 3;
    int nodeA = node0 + w * 16 + gid;
    int nodeB = nodeA + 8;
    bool vA = nodeA < N_NODES, vB = nodeB < N_NODES;
    float*    Y1f = reinterpret_cast<float*>(g_Y1);
    uint32_t* Y2u = reinterpret_cast<uint32_t*>(g_Y2h);

#pragma unroll
    for (int nt = 0; nt < 8; nt++) {          // cols 0..63 -> Y1 (+bias, fp32)
        int c = nt * 8 + tig * 2;
        float b0 = bias_s[c], b1 = bias_s[c + 1];
        if (vA) *(float2*)&Y1f[(size_t)nodeA * 64 + c] =
            make_float2(acc[nt][0] + b0, acc[nt][1] + b1);
        if (vB) *(float2*)&Y1f[(size_t)nodeB * 64 + c] =
            make_float2(acc[nt][2] + b0, acc[nt][3] + b1);
    }
#pragma unroll
    for (int nt = 8; nt < 16; nt++) {         // cols 64..127 -> Y2 (fp16)
        int c = (nt - 8) * 8 + tig * 2;
        if (vA) {
            __half2 h = __floats2half2_rn(acc[nt][0], acc[nt][1]);
            Y2u[(size_t)nodeA * 32 + (c >> 1)] = *(uint32_t*)&h;
        }
        if (vB) {
            __half2 h = __floats2half2_rn(acc[nt][2], acc[nt][3]);
            Y2u[(size_t)nodeB * 32 + (c >> 1)] = *(uint32_t*)&h;
        }
    }
}

// ---------------------------------------------------------------------------
// K5 (join): gather over Y2h + Y1 add + L2 normalize -> final out.
// 8 lanes/node; batch-8 row loads with NEXT batch's edge records prefetched
// before current rows issue (one L2 round trip per batch instead of two).
// ---------------------------------------------------------------------------
__global__ __launch_bounds__(256)
void gather2_kernel(float4* __restrict__ out4) {
    int t = blockIdx.x * blockDim.x + threadIdx.x;
    int n    = t >> 3;
    int lane = t & 7;
    if (n >= N_NODES) return;

    int j0 = g_start[n];
    int j1 = g_start[n + 1];

    float a[8] = {0.f, 0.f, 0.f, 0.f, 0.f, 0.f, 0.f, 0.f};

    if (j0 < j1) {
        int2 r[8];
#pragma unroll
        for (int e = 0; e < 8; e++)
            r[e] = (j0 + e < j1) ? __ldg(&g_edges[j0 + e]) : make_int2(0, 0);

        int j = j0;
        while (true) {
            int jn = j + 8;
            bool more = jn < j1;
            // prefetch next batch's records (overlaps with row loads below)
            int2 rn[8];
            if (more) {
#pragma unroll
                for (int e = 0; e < 8; e++)
                    rn[e] = (jn + e < j1) ? __ldg(&g_edges[jn + e]) : make_int2(0, 0);
            }
            // row loads + accumulate
#pragma unroll
            for (int e = 0; e < 8; e++) {
                uint4 h = __ldg(&g_Y2h[(size_t)r[e].x * 8 + lane]);
                float w = __int_as_float(r[e].y);
                float2 p0 = __half22float2(*(__half2*)&h.x);
                float2 p1 = __half22float2(*(__half2*)&h.y);
                float2 p2 = __half22float2(*(__half2*)&h.z);
                float2 p3 = __half22float2(*(__half2*)&h.w);
                a[0] += w * p0.x; a[1] += w * p0.y;
                a[2] += w * p1.x; a[3] += w * p1.y;
                a[4] += w * p2.x; a[5] += w * p2.y;
                a[6] += w * p3.x; a[7] += w * p3.y;
            }
            if (!more) break;
#pragma unroll
            for (int e = 0; e < 8; e++) r[e] = rn[e];
            j = jn;
        }
    }

    float4 y1a = g_Y1[(size_t)n * 16 + lane * 2];
    float4 y1b = g_Y1[(size_t)n * 16 + lane * 2 + 1];
    a[0] += y1a.x; a[1] += y1a.y; a[2] += y1a.z; a[3] += y1a.w;
    a[4] += y1b.x; a[5] += y1b.y; a[6] += y1b.z; a[7] += y1b.w;

    float ss = 0.f;
#pragma unroll
    for (int i = 0; i < 8; i++) ss += a[i] * a[i];
    ss += __shfl_xor_sync(0xffffffffu, ss, 1);
    ss += __shfl_xor_sync(0xffffffffu, ss, 2);
    ss += __shfl_xor_sync(0xffffffffu, ss, 4);
    float inv = 1.0f / fmaxf(sqrtf(ss), 1e-12f);

    out4[(size_t)n * 16 + lane * 2] =
        make_float4(a[0] * inv, a[1] * inv, a[2] * inv, a[3] * inv);
    out4[(size_t)n * 16 + lane * 2 + 1] =
        make_float4(a[4] * inv, a[5] * inv, a[6] * inv, a[7] * inv);
}

// ---------------------------------------------------------------------------
// Launch graph:
//   main:  [fork] -> prepB -> hmma --------\
//   side:  hist -> scan -> fill -> [join] -> gather2
// inputs: 0 features[50000,64] f32  1 edge_src[800000] i32  2 edge_dst i32
//         3 edge_weight f32         4 W[64,128] f32         5 b[64] f32
// ---------------------------------------------------------------------------
extern "C" void kernel_launch(void* const* d_in, const int* in_sizes, int n_in,
                              void* d_out, int out_size) {
    const float4* feat4 = (const float4*)d_in[0];
    const int*    esrc  = (const int*)d_in[1];
    const int*    edst  = (const int*)d_in[2];
    const float*  ew    = (const float*)d_in[3];
    const float*  W     = (const float*)d_in[4];
    const float*  bias  = (const float*)d_in[5];
    float4*       out4  = (float4*)d_out;

    static cudaStream_t s2 = nullptr;
    static cudaEvent_t  evF = nullptr, evJ = nullptr;
    if (s2 == nullptr) {
        cudaStreamCreateWithFlags(&s2, cudaStreamNonBlocking);
        cudaEventCreateWithFlags(&evF, cudaEventDisableTiming);
        cudaEventCreateWithFlags(&evJ, cudaEventDisableTiming);
    }

    int4* rank4;
    cudaGetSymbolAddress((void**)&rank4, g_rank);

    // fork side branch off the capture stream
    cudaEventRecord(evF, 0);
    cudaStreamWaitEvent(s2, evF, 0);

    // side: CSR build
    hist_kernel<<<(N_EDGES / 4 + 255) / 256, 256, 0, s2>>>((const int4*)edst, rank4);
    scan_kernel<<<SCAN_BLOCKS, 256, 0, s2>>>();
    fill_kernel<<<(N_EDGES / 4 + 255) / 256, 256, 0, s2>>>(
        (const int4*)esrc, (const int4*)edst, (const float4*)ew,
        (const int4*)rank4);
    cudaEventRecord(evJ, s2);

    // main: B build + HMMA GEMM (concurrent with CSR build)
    prepB_kernel<<<4, 256>>>(W);
    hmma_kernel<<<N_TILES, 256>>>(feat4, bias);

    // join, then terminal gather
    cudaStreamWaitEvent(0, evJ, 0);
    {
        long long threads = (long long)N_NODES * 8;
        gather2_kernel<<<(int)((threads + 255) / 256), 256>>>(out4);
    }

    (void)in_sizes; (void)n_in; (void)out_size;
}